// round 1
// baseline (speedup 1.0000x reference)
#include <cuda_runtime.h>

// ---------------------------------------------------------------------------
// Problem constants (B=512 fixed by the reference)
//   conv layers: (C, H) = (64,27)(192,27)(384,13)(256,13)(256,13)
//   per-batch lens: 46656, 139968, 64896, 43264, 43264
//   fc dense slots: 4096, 4096, 1000
//   coef layout (concatenated): conv0..4 | fc0 | fc1 | fc2  = 347240 floats
// ---------------------------------------------------------------------------
#define NCOEF      347240
#define CONV_COEF  338048
#define CHUNK      8192
#define NCHUNK     47
#define BPB        4          // batches per block in main kernel
#define TPB        256
#define NB         512

__device__ __align__(16) float g_coef[347264];
__device__ float g_scratch[NB * NCHUNK];

// ---------------------------------------------------------------------------
// Kernel 1: build the coefficient vector.
//   conv region:  coef[p] = mass_l[hw] * W[convWoff_l + c]
//   fc0/fc1 region: zeroed (scatter kernel fills selected slots)
//   fc2 region:   coef = s * W[3200 + c]
// ---------------------------------------------------------------------------
__global__ void build_coef(const float* __restrict__ m0, const float* __restrict__ m1,
                           const float* __restrict__ m2, const float* __restrict__ m3,
                           const float* __restrict__ m4,
                           const float* __restrict__ W, const float* __restrict__ mfc)
{
    int p = blockIdx.x * blockDim.x + threadIdx.x;
    if (p >= NCOEF) return;
    if (p < CONV_COEF) {
        const float* mass; int hh, wOff, q;
        if      (p <  46656) { mass = m0; hh = 729; wOff =   0; q = p; }
        else if (p < 186624) { mass = m1; hh = 729; wOff =  64; q = p -  46656; }
        else if (p < 251520) { mass = m2; hh = 169; wOff = 256; q = p - 186624; }
        else if (p < 294784) { mass = m3; hh = 169; wOff = 640; q = p - 251520; }
        else                 { mass = m4; hh = 169; wOff = 896; q = p - 294784; }
        int c  = q / hh;
        int hw = q - c * hh;
        g_coef[p] = mass[hw] * W[wOff + c];
    } else if (p < 346240) {
        g_coef[p] = 0.0f;              // fc0/fc1 dense slots, scattered later
    } else {
        int c = p - 346240;            // fc2 (1000 dense)
        g_coef[p] = mfc[0] * W[3200 + c];
    }
}

// ---------------------------------------------------------------------------
// Kernel 2: scatter fc0/fc1 selection weights. Handles idx dtype int32 OR
// int64 at runtime: if the buffer is int32, word[1] (as int64) combines two
// sorted-unique indices -> value >= 2^32; if genuinely int64 it's < 4096.
// ---------------------------------------------------------------------------
__global__ void scatter_fc(const void* __restrict__ i0, const void* __restrict__ i1,
                           const float* __restrict__ W, const float* __restrict__ mfc)
{
    int k = blockIdx.x * blockDim.x + threadIdx.x;
    if (k >= 2048) return;
    const void* ip = (k < 1024) ? i0 : i1;
    int kk = k & 1023;
    long long probe = ((const long long*)ip)[1];
    int idx;
    if (probe >= 0 && probe < 4096) idx = (int)((const long long*)ip)[kk];  // int64
    else                            idx = ((const int*)ip)[kk];             // int32
    float s = mfc[0];
    if (k < 1024) g_coef[338048 + idx] = s * W[1152 + kk];
    else          g_coef[342144 + idx] = s * W[2176 + kk];
}

// ---------------------------------------------------------------------------
// Kernel 3: main streaming dot. grid = (47 chunks, 512/BPB batch groups).
// Each block: one 8192-float slice of one layer, for BPB consecutive batches.
// coef slice read once per block (L2-resident), fmap rows streamed from HBM.
// ---------------------------------------------------------------------------
__global__ void __launch_bounds__(TPB)
main_dot(const float* __restrict__ f0, const float* __restrict__ f1,
         const float* __restrict__ f2, const float* __restrict__ f3,
         const float* __restrict__ f4, const float* __restrict__ c0,
         const float* __restrict__ c1, const float* __restrict__ c2)
{
    const int chunkStart[9] = {0, 6, 24, 32, 38, 44, 45, 46, 47};
    const int layerLen[8]   = {46656, 139968, 64896, 43264, 43264, 4096, 4096, 1000};
    const int coefOff[8]    = {0, 46656, 186624, 251520, 294784, 338048, 342144, 346240};

    int chunk = blockIdx.x;
    int layer = 0;
#pragma unroll
    for (int l = 1; l < 8; l++) if (chunk >= chunkStart[l]) layer = l;

    int len  = layerLen[layer];
    int base = (chunk - chunkStart[layer]) * CHUNK;
    int n    = min(CHUNK, len - base);

    const float* in;
    switch (layer) {
        case 0: in = f0; break; case 1: in = f1; break;
        case 2: in = f2; break; case 3: in = f3; break;
        case 4: in = f4; break; case 5: in = c0; break;
        case 6: in = c1; break; default: in = c2; break;
    }

    int b0 = blockIdx.y * BPB;
    const float4* cf = (const float4*)(g_coef + coefOff[layer] + base);
    const float*  p0 = in + (size_t)b0 * len + base;
    const float4* r0 = (const float4*)(p0);
    const float4* r1 = (const float4*)(p0 + (size_t)len);
    const float4* r2 = (const float4*)(p0 + 2 * (size_t)len);
    const float4* r3 = (const float4*)(p0 + 3 * (size_t)len);
    int n4 = n >> 2;   // all lens are multiples of 4

    float a0 = 0.f, a1 = 0.f, a2 = 0.f, a3 = 0.f;
    for (int i = threadIdx.x; i < n4; i += TPB) {
        float4 cv = cf[i];
        float4 v0 = r0[i];
        float4 v1 = r1[i];
        float4 v2 = r2[i];
        float4 v3 = r3[i];
        a0 += cv.x*v0.x + cv.y*v0.y + cv.z*v0.z + cv.w*v0.w;
        a1 += cv.x*v1.x + cv.y*v1.y + cv.z*v1.z + cv.w*v1.w;
        a2 += cv.x*v2.x + cv.y*v2.y + cv.z*v2.z + cv.w*v2.w;
        a3 += cv.x*v3.x + cv.y*v3.y + cv.z*v3.z + cv.w*v3.w;
    }

    // warp reduce
#pragma unroll
    for (int off = 16; off > 0; off >>= 1) {
        a0 += __shfl_down_sync(0xFFFFFFFFu, a0, off);
        a1 += __shfl_down_sync(0xFFFFFFFFu, a1, off);
        a2 += __shfl_down_sync(0xFFFFFFFFu, a2, off);
        a3 += __shfl_down_sync(0xFFFFFFFFu, a3, off);
    }
    __shared__ float sred[4][TPB / 32];
    int warp = threadIdx.x >> 5, lane = threadIdx.x & 31;
    if (lane == 0) { sred[0][warp]=a0; sred[1][warp]=a1; sred[2][warp]=a2; sred[3][warp]=a3; }
    __syncthreads();
    if (threadIdx.x < BPB) {
        float t = 0.f;
#pragma unroll
        for (int w = 0; w < TPB / 32; w++) t += sred[threadIdx.x][w];
        g_scratch[(size_t)(b0 + threadIdx.x) * NCHUNK + chunk] = t;
    }
}

// ---------------------------------------------------------------------------
// Kernel 4: finish — sum the 47 partials per batch, add bias.
// ---------------------------------------------------------------------------
__global__ void finish(const float* __restrict__ bias, float* __restrict__ out, int B)
{
    int b = blockIdx.x * blockDim.x + threadIdx.x;
    if (b >= B) return;
    float t = bias[0];
#pragma unroll 1
    for (int j = 0; j < NCHUNK; j++) t += g_scratch[(size_t)b * NCHUNK + j];
    out[b] = t;
}

// ---------------------------------------------------------------------------
// Host launcher. Inputs are identified by element count (all sizes unique up
// to same-shape groups; within a group, order is preserved in any plausible
// metadata ordering: mass0<mass1, mass2<mass3<mass4, fmap3<fmap4, fc0<fc1,
// idx0<idx1, mfc<b).
// ---------------------------------------------------------------------------
extern "C" void kernel_launch(void* const* d_in, const int* in_sizes, int n_in,
                              void* d_out, int out_size)
{
    const float *f[5] = {0}, *fc[3] = {0}, *mass[5] = {0}, *W = 0, *bias = 0, *mfc = 0;
    const void  *idx[2] = {0};
    int nf34 = 0, nfc01 = 0, nidx = 0, n729 = 0, n169 = 0, nOne = 0;

    for (int i = 0; i < n_in; i++) {
        int sz = in_sizes[i];
        const void* p = d_in[i];
        if      (sz == 23887872) f[0] = (const float*)p;
        else if (sz == 71663616) f[1] = (const float*)p;
        else if (sz == 33226752) f[2] = (const float*)p;
        else if (sz == 22151168) { if (nf34 < 2) f[3 + nf34++] = (const float*)p; }
        else if (sz ==  2097152) { if (nfc01 < 2) fc[nfc01++] = (const float*)p; }
        else if (sz ==   512000) fc[2] = (const float*)p;
        else if (sz ==     1024) { if (nidx < 2) idx[nidx++] = p; }
        else if (sz ==     4200) W = (const float*)p;
        else if (sz ==      729) { if (n729 < 2) mass[n729++] = (const float*)p; }
        else if (sz ==      169) { if (n169 < 3) mass[2 + n169++] = (const float*)p; }
        else if (sz ==        1) { if (nOne++ == 0) mfc = (const float*)p; else bias = (const float*)p; }
    }

    build_coef<<<(NCOEF + 255) / 256, 256>>>(mass[0], mass[1], mass[2], mass[3], mass[4], W, mfc);
    scatter_fc<<<8, 256>>>(idx[0], idx[1], W, mfc);
    main_dot<<<dim3(NCHUNK, NB / BPB), TPB>>>(f[0], f[1], f[2], f[3], f[4], fc[0], fc[1], fc[2]);
    int B = out_size;
    finish<<<(B + 255) / 256, 256>>>(bias, (float*)d_out, B);
}

// round 3
// speedup vs baseline: 1.0671x; 1.0671x over previous
#include <cuda_runtime.h>

// ---------------------------------------------------------------------------
// Problem constants (B=512 fixed by the reference)
//   conv layers: (C, H) = (64,27)(192,27)(384,13)(256,13)(256,13)
//   per-batch lens: 46656, 139968, 64896, 43264, 43264
//   fc dense slots: 4096, 4096, 1000
//   coef layout (concatenated): conv0..4 | fc0 | fc1 | fc2  = 347240 floats
// ---------------------------------------------------------------------------
#define NCOEF      347240
#define CONV_COEF  338048
#define CHUNK      8192
#define NCHUNK     47
#define BPB        8          // batches per block in main kernel
#define TPB        256
#define NB         512

__device__ __align__(16) float g_coef[347264];
__device__ float g_scratch[NB * NCHUNK];

// ---------------------------------------------------------------------------
// Kernel 1: build the coefficient vector.
// ---------------------------------------------------------------------------
__global__ void build_coef(const float* __restrict__ m0, const float* __restrict__ m1,
                           const float* __restrict__ m2, const float* __restrict__ m3,
                           const float* __restrict__ m4,
                           const float* __restrict__ W, const float* __restrict__ mfc)
{
    int p = blockIdx.x * blockDim.x + threadIdx.x;
    if (p >= NCOEF) return;
    if (p < CONV_COEF) {
        const float* mass; int hh, wOff, q;
        if      (p <  46656) { mass = m0; hh = 729; wOff =   0; q = p; }
        else if (p < 186624) { mass = m1; hh = 729; wOff =  64; q = p -  46656; }
        else if (p < 251520) { mass = m2; hh = 169; wOff = 256; q = p - 186624; }
        else if (p < 294784) { mass = m3; hh = 169; wOff = 640; q = p - 251520; }
        else                 { mass = m4; hh = 169; wOff = 896; q = p - 294784; }
        int c  = q / hh;
        int hw = q - c * hh;
        g_coef[p] = mass[hw] * W[wOff + c];
    } else if (p < 346240) {
        g_coef[p] = 0.0f;              // fc0/fc1 dense slots, scattered later
    } else {
        int c = p - 346240;            // fc2 (1000 dense)
        g_coef[p] = mfc[0] * W[3200 + c];
    }
}

// ---------------------------------------------------------------------------
// Kernel 2: scatter fc0/fc1 selection weights (idx dtype int32/int64 probed).
// ---------------------------------------------------------------------------
__global__ void scatter_fc(const void* __restrict__ i0, const void* __restrict__ i1,
                           const float* __restrict__ W, const float* __restrict__ mfc)
{
    int k = blockIdx.x * blockDim.x + threadIdx.x;
    if (k >= 2048) return;
    const void* ip = (k < 1024) ? i0 : i1;
    int kk = k & 1023;
    long long probe = ((const long long*)ip)[1];
    int idx;
    if (probe >= 0 && probe < 4096) idx = (int)((const long long*)ip)[kk];  // int64
    else                            idx = ((const int*)ip)[kk];             // int32
    float s = mfc[0];
    if (k < 1024) g_coef[338048 + idx] = s * W[1152 + kk];
    else          g_coef[342144 + idx] = s * W[2176 + kk];
}

// ---------------------------------------------------------------------------
// Kernel 3: main streaming dot. grid = (47 chunks, 512/BPB batch groups).
// Each block: one 8192-float slice of one layer, for BPB consecutive batches.
// coef slice read once per block (L2-resident), fmap rows streamed from HBM.
// ---------------------------------------------------------------------------
__global__ void __launch_bounds__(TPB)
main_dot(const float* __restrict__ f0, const float* __restrict__ f1,
         const float* __restrict__ f2, const float* __restrict__ f3,
         const float* __restrict__ f4, const float* __restrict__ c0,
         const float* __restrict__ c1, const float* __restrict__ c2)
{
    const int chunkStart[9] = {0, 6, 24, 32, 38, 44, 45, 46, 47};
    const int layerLen[8]   = {46656, 139968, 64896, 43264, 43264, 4096, 4096, 1000};
    const int coefOff[8]    = {0, 46656, 186624, 251520, 294784, 338048, 342144, 346240};

    int chunk = blockIdx.x;
    int layer = 0;
#pragma unroll
    for (int l = 1; l < 8; l++) if (chunk >= chunkStart[l]) layer = l;

    int len  = layerLen[layer];
    int base = (chunk - chunkStart[layer]) * CHUNK;
    int n    = min(CHUNK, len - base);

    const float* in;
    switch (layer) {
        case 0: in = f0; break; case 1: in = f1; break;
        case 2: in = f2; break; case 3: in = f3; break;
        case 4: in = f4; break; case 5: in = c0; break;
        case 6: in = c1; break; default: in = c2; break;
    }

    int b0 = blockIdx.y * BPB;
    const float4* cf = (const float4*)(g_coef + coefOff[layer] + base);
    const float*  p0 = in + (size_t)b0 * len + base;
    int n4 = n >> 2;   // all lens are multiples of 4

    float acc[BPB];
#pragma unroll
    for (int r = 0; r < BPB; r++) acc[r] = 0.f;

    for (int i = threadIdx.x; i < n4; i += TPB) {
        float4 cv = cf[i];
#pragma unroll
        for (int r = 0; r < BPB; r++) {
            float4 v = ((const float4*)(p0 + (size_t)r * len))[i];
            acc[r] += cv.x*v.x + cv.y*v.y + cv.z*v.z + cv.w*v.w;
        }
    }

    // warp reduce each accumulator
#pragma unroll
    for (int off = 16; off > 0; off >>= 1)
#pragma unroll
        for (int r = 0; r < BPB; r++)
            acc[r] += __shfl_down_sync(0xFFFFFFFFu, acc[r], off);

    __shared__ float sred[BPB][TPB / 32];
    int warp = threadIdx.x >> 5, lane = threadIdx.x & 31;
    if (lane == 0)
#pragma unroll
        for (int r = 0; r < BPB; r++) sred[r][warp] = acc[r];
    __syncthreads();
    if (threadIdx.x < BPB) {
        float t = 0.f;
#pragma unroll
        for (int w = 0; w < TPB / 32; w++) t += sred[threadIdx.x][w];
        g_scratch[(size_t)(b0 + threadIdx.x) * NCHUNK + chunk] = t;
    }
}

// ---------------------------------------------------------------------------
// Kernel 4: finish — one warp per batch, parallel load of the 47 partials,
// shuffle reduce, add bias. Launched with B*32 threads total (64 blocks x 256).
// ---------------------------------------------------------------------------
__global__ void __launch_bounds__(256)
finish(const float* __restrict__ bias, float* __restrict__ out, int B)
{
    int warpGlobal = (blockIdx.x * blockDim.x + threadIdx.x) >> 5;
    int lane = threadIdx.x & 31;
    if (warpGlobal >= B) return;
    const float* s = g_scratch + (size_t)warpGlobal * NCHUNK;
    float t = s[lane];                          // lanes 0..31 read partials 0..31
    if (lane < NCHUNK - 32) t += s[32 + lane];  // lanes 0..14 pick up 32..46
#pragma unroll
    for (int off = 16; off > 0; off >>= 1)
        t += __shfl_down_sync(0xFFFFFFFFu, t, off);
    if (lane == 0) out[warpGlobal] = t + bias[0];
}

// ---------------------------------------------------------------------------
// Host launcher. Inputs identified by element count (stable within groups).
// ---------------------------------------------------------------------------
extern "C" void kernel_launch(void* const* d_in, const int* in_sizes, int n_in,
                              void* d_out, int out_size)
{
    const float *f[5] = {0}, *fc[3] = {0}, *mass[5] = {0}, *W = 0, *bias = 0, *mfc = 0;
    const void  *idx[2] = {0};
    int nf34 = 0, nfc01 = 0, nidx = 0, n729 = 0, n169 = 0, nOne = 0;

    for (int i = 0; i < n_in; i++) {
        int sz = in_sizes[i];
        const void* p = d_in[i];
        if      (sz == 23887872) f[0] = (const float*)p;
        else if (sz == 71663616) f[1] = (const float*)p;
        else if (sz == 33226752) f[2] = (const float*)p;
        else if (sz == 22151168) { if (nf34 < 2) f[3 + nf34++] = (const float*)p; }
        else if (sz ==  2097152) { if (nfc01 < 2) fc[nfc01++] = (const float*)p; }
        else if (sz ==   512000) fc[2] = (const float*)p;
        else if (sz ==     1024) { if (nidx < 2) idx[nidx++] = p; }
        else if (sz ==     4200) W = (const float*)p;
        else if (sz ==      729) { if (n729 < 2) mass[n729++] = (const float*)p; }
        else if (sz ==      169) { if (n169 < 3) mass[2 + n169++] = (const float*)p; }
        else if (sz ==        1) { if (nOne++ == 0) mfc = (const float*)p; else bias = (const float*)p; }
    }

    build_coef<<<(NCOEF + 255) / 256, 256>>>(mass[0], mass[1], mass[2], mass[3], mass[4], W, mfc);
    scatter_fc<<<8, 256>>>(idx[0], idx[1], W, mfc);
    main_dot<<<dim3(NCHUNK, NB / BPB), TPB>>>(f[0], f[1], f[2], f[3], f[4], fc[0], fc[1], fc[2]);
    int B = out_size;
    // one warp per batch element -> B*32 threads
    finish<<<(B * 32 + 255) / 256, 256>>>(bias, (float*)d_out, B);
}

// round 4
// speedup vs baseline: 1.0790x; 1.0112x over previous
#include <cuda_runtime.h>

// ---------------------------------------------------------------------------
// Problem constants (B=512 fixed by the reference)
//   conv layers: (C, H) = (64,27)(192,27)(384,13)(256,13)(256,13)
//   per-batch lens: 46656, 139968, 64896, 43264, 43264
//   fc dense slots: 4096, 4096, 1000
//   coef layout (concatenated): conv0..4 | fc0 | fc1 | fc2  = 347240 floats
// ---------------------------------------------------------------------------
#define NCOEF      347240
#define CONV_COEF  338048
#define CHUNK      8192
#define NCHUNK     47
#define BPB        8          // batches per block in main kernel
#define TPB        256
#define NB         512
#define NYGRP      (NB / BPB) // 64

__device__ __align__(16) float g_coef[347264];
__device__ float g_scratch[NB * NCHUNK];
__device__ int   g_cnt[NYGRP];

// ---------------------------------------------------------------------------
// idx element fetch with runtime dtype probe (int32 vs int64).
// Sorted unique indices < 4096: if int64, word[1] in [0,4096); if int32,
// word[1] packs (idx[2],idx[3]) with idx[3]>=3 -> value >= 2^32.
// ---------------------------------------------------------------------------
__device__ __forceinline__ int idx_at(const void* ip, bool is64, int k) {
    return is64 ? (int)((const long long*)ip)[k] : ((const int*)ip)[k];
}

// ---------------------------------------------------------------------------
// Kernel 1: fused setup. Builds the whole coefficient vector (fc0/fc1 slots
// via binary search over sorted idx), and zeroes the completion counters
// (required every graph replay).
// ---------------------------------------------------------------------------
__global__ void setup(const float* __restrict__ m0, const float* __restrict__ m1,
                      const float* __restrict__ m2, const float* __restrict__ m3,
                      const float* __restrict__ m4,
                      const float* __restrict__ W, const float* __restrict__ mfc,
                      const void* __restrict__ i0, const void* __restrict__ i1)
{
    int p = blockIdx.x * blockDim.x + threadIdx.x;
    if (p < NYGRP) g_cnt[p] = 0;
    if (p >= NCOEF) return;

    if (p < CONV_COEF) {
        const float* mass; int hh, wOff, q;
        if      (p <  46656) { mass = m0; hh = 729; wOff =   0; q = p; }
        else if (p < 186624) { mass = m1; hh = 729; wOff =  64; q = p -  46656; }
        else if (p < 251520) { mass = m2; hh = 169; wOff = 256; q = p - 186624; }
        else if (p < 294784) { mass = m3; hh = 169; wOff = 640; q = p - 251520; }
        else                 { mass = m4; hh = 169; wOff = 896; q = p - 294784; }
        int c  = q / hh;
        int hw = q - c * hh;
        g_coef[p] = mass[hw] * W[wOff + c];
    } else if (p < 346240) {
        // fc0 slots [338048,342144), fc1 slots [342144,346240)
        bool isFc1 = (p >= 342144);
        int slot = p - (isFc1 ? 342144 : 338048);
        const void* ip = isFc1 ? i1 : i0;
        long long probe = ((const long long*)ip)[1];
        bool is64 = (probe >= 0 && probe < 4096);
        // binary search for slot in sorted idx[0..1023]
        int lo = 0, hi = 1023, found = -1;
        while (lo <= hi) {
            int mid = (lo + hi) >> 1;
            int v = idx_at(ip, is64, mid);
            if (v == slot) { found = mid; break; }
            if (v < slot) lo = mid + 1; else hi = mid - 1;
        }
        g_coef[p] = (found >= 0) ? mfc[0] * W[(isFc1 ? 2176 : 1152) + found] : 0.0f;
    } else {
        int c = p - 346240;            // fc2 (1000 dense)
        g_coef[p] = mfc[0] * W[3200 + c];
    }
}

// ---------------------------------------------------------------------------
// Kernel 2: main streaming dot + fused deterministic final reduction.
// grid = (47 chunks, 64 y-groups). Each block: one 8192-float slice of one
// layer, for BPB=8 consecutive batches. fmap streamed with .cs (evict-first),
// coef slice L2-resident. The last block to finish in each y-group reduces
// the 47x8 partials in a FIXED order and writes out[b] = sum + bias.
// ---------------------------------------------------------------------------
__global__ void __launch_bounds__(TPB)
main_dot(const float* __restrict__ f0, const float* __restrict__ f1,
         const float* __restrict__ f2, const float* __restrict__ f3,
         const float* __restrict__ f4, const float* __restrict__ c0,
         const float* __restrict__ c1, const float* __restrict__ c2,
         const float* __restrict__ bias, float* __restrict__ out)
{
    const int chunkStart[9] = {0, 6, 24, 32, 38, 44, 45, 46, 47};
    const int layerLen[8]   = {46656, 139968, 64896, 43264, 43264, 4096, 4096, 1000};
    const int coefOff[8]    = {0, 46656, 186624, 251520, 294784, 338048, 342144, 346240};

    int chunk = blockIdx.x;
    int layer = 0;
#pragma unroll
    for (int l = 1; l < 8; l++) if (chunk >= chunkStart[l]) layer = l;

    int len  = layerLen[layer];
    int base = (chunk - chunkStart[layer]) * CHUNK;
    int n    = min(CHUNK, len - base);

    const float* in;
    switch (layer) {
        case 0: in = f0; break; case 1: in = f1; break;
        case 2: in = f2; break; case 3: in = f3; break;
        case 4: in = f4; break; case 5: in = c0; break;
        case 6: in = c1; break; default: in = c2; break;
    }

    int b0 = blockIdx.y * BPB;
    const float4* cf = (const float4*)(g_coef + coefOff[layer] + base);
    const float*  p0 = in + (size_t)b0 * len + base;
    int n4 = n >> 2;   // all lens are multiples of 4

    float acc[BPB];
#pragma unroll
    for (int r = 0; r < BPB; r++) acc[r] = 0.f;

    for (int i = threadIdx.x; i < n4; i += TPB) {
        float4 cv = __ldg(cf + i);
#pragma unroll
        for (int r = 0; r < BPB; r++) {
            float4 v = __ldcs((const float4*)(p0 + (size_t)r * len) + i);
            acc[r] += cv.x*v.x + cv.y*v.y + cv.z*v.z + cv.w*v.w;
        }
    }

    // warp reduce each accumulator
#pragma unroll
    for (int off = 16; off > 0; off >>= 1)
#pragma unroll
        for (int r = 0; r < BPB; r++)
            acc[r] += __shfl_down_sync(0xFFFFFFFFu, acc[r], off);

    __shared__ float sred[BPB][TPB / 32];
    __shared__ int sIsLast;
    int warp = threadIdx.x >> 5, lane = threadIdx.x & 31;
    if (lane == 0)
#pragma unroll
        for (int r = 0; r < BPB; r++) sred[r][warp] = acc[r];
    __syncthreads();
    if (threadIdx.x < BPB) {
        float t = 0.f;
#pragma unroll
        for (int w = 0; w < TPB / 32; w++) t += sred[threadIdx.x][w];
        g_scratch[(size_t)(b0 + threadIdx.x) * NCHUNK + chunk] = t;
    }
    // make partials globally visible before signaling completion
    __threadfence();
    __syncthreads();
    if (threadIdx.x == 0) {
        int old = atomicAdd(&g_cnt[blockIdx.y], 1);
        sIsLast = (old == NCHUNK - 1);
    }
    __syncthreads();

    if (sIsLast) {
        // last block of this y-group: reduce 47 partials for each of 8 batches.
        // warp r handles batch b0+r; fixed summation order -> deterministic.
        if (warp < BPB) {
            const float* s = g_scratch + (size_t)(b0 + warp) * NCHUNK;
            float t = __ldcg(s + lane);
            if (lane < NCHUNK - 32) t += __ldcg(s + 32 + lane);
#pragma unroll
            for (int off = 16; off > 0; off >>= 1)
                t += __shfl_down_sync(0xFFFFFFFFu, t, off);
            if (lane == 0) out[b0 + warp] = t + bias[0];
        }
    }
}

// ---------------------------------------------------------------------------
// Host launcher. Inputs identified by element count (stable within groups).
// ---------------------------------------------------------------------------
extern "C" void kernel_launch(void* const* d_in, const int* in_sizes, int n_in,
                              void* d_out, int out_size)
{
    const float *f[5] = {0}, *fc[3] = {0}, *mass[5] = {0}, *W = 0, *bias = 0, *mfc = 0;
    const void  *idx[2] = {0};
    int nf34 = 0, nfc01 = 0, nidx = 0, n729 = 0, n169 = 0, nOne = 0;

    for (int i = 0; i < n_in; i++) {
        int sz = in_sizes[i];
        const void* p = d_in[i];
        if      (sz == 23887872) f[0] = (const float*)p;
        else if (sz == 71663616) f[1] = (const float*)p;
        else if (sz == 33226752) f[2] = (const float*)p;
        else if (sz == 22151168) { if (nf34 < 2) f[3 + nf34++] = (const float*)p; }
        else if (sz ==  2097152) { if (nfc01 < 2) fc[nfc01++] = (const float*)p; }
        else if (sz ==   512000) fc[2] = (const float*)p;
        else if (sz ==     1024) { if (nidx < 2) idx[nidx++] = p; }
        else if (sz ==     4200) W = (const float*)p;
        else if (sz ==      729) { if (n729 < 2) mass[n729++] = (const float*)p; }
        else if (sz ==      169) { if (n169 < 3) mass[2 + n169++] = (const float*)p; }
        else if (sz ==        1) { if (nOne++ == 0) mfc = (const float*)p; else bias = (const float*)p; }
    }

    setup<<<(NCOEF + 255) / 256, 256>>>(mass[0], mass[1], mass[2], mass[3], mass[4],
                                        W, mfc, idx[0], idx[1]);
    main_dot<<<dim3(NCHUNK, NYGRP), TPB>>>(f[0], f[1], f[2], f[3], f[4],
                                           fc[0], fc[1], fc[2],
                                           bias, (float*)d_out);
}

// round 7
// speedup vs baseline: 1.0861x; 1.0066x over previous
#include <cuda_runtime.h>

// ---------------------------------------------------------------------------
// Single-kernel formulation. B=512.
//   conv layers: (C,H) = (64,27)(192,27)(384,13)(256,13)(256,13)
//   per-batch lens: 46656, 139968, 64896, 43264, 43264
//   fc: 4096 (masked 1024), 4096 (masked 1024), 1000 dense
//   virtual coef vector: conv0..4 | fc0 | fc1 | fc2 = 347240 floats, but each
//   block computes its own 2048-float slice into smem (no setup kernel).
// ---------------------------------------------------------------------------
#define CHUNK   2048
#define NCHUNK  173            // 23+69+32+22+22+2+2+1
#define BPB     8              // batches per block
#define TPB     256
#define NB      512
#define NYGRP   (NB / BPB)     // 64

__device__ float g_scratch[NB * NCHUNK];
__device__ int   g_cnt[NYGRP];   // zero-init at load; last block re-zeros per replay

__device__ __forceinline__ int idx_at(const void* ip, bool is64, int k) {
    return is64 ? (int)((const long long*)ip)[k] : ((const int*)ip)[k];
}

// ---------------------------------------------------------------------------
// grid = (NCHUNK, NYGRP). Each block:
//   1) builds its 2048-float coef slice in smem (conv: mass*W; fc: scatter)
//   2) streams BPB=8 batch rows of its slice from HBM (__ldcs, evict-first)
//   3) block-reduces, writes 8 partials
//   4) last block of the y-group sums the 173 partials per batch (fixed
//      order -> deterministic), adds bias, writes out, resets counter.
// ---------------------------------------------------------------------------
__global__ void __launch_bounds__(TPB)
fused_dot(const float* __restrict__ f0, const float* __restrict__ f1,
          const float* __restrict__ f2, const float* __restrict__ f3,
          const float* __restrict__ f4, const float* __restrict__ c0,
          const float* __restrict__ c1, const float* __restrict__ c2,
          const float* __restrict__ m0, const float* __restrict__ m1,
          const float* __restrict__ m2, const float* __restrict__ m3,
          const float* __restrict__ m4,
          const float* __restrict__ W, const float* __restrict__ mfc,
          const void* __restrict__ i0, const void* __restrict__ i1,
          const float* __restrict__ bias, float* __restrict__ out)
{
    const int chunkStart[9] = {0, 23, 92, 124, 146, 168, 170, 172, 173};
    const int layerLen[8]   = {46656, 139968, 64896, 43264, 43264, 4096, 4096, 1000};

    __shared__ __align__(16) float s_coef[CHUNK];
    __shared__ float sred[BPB][TPB / 32];
    __shared__ int sIsLast;

    int chunk = blockIdx.x;
    int layer = 0;
#pragma unroll
    for (int l = 1; l < 8; l++) if (chunk >= chunkStart[l]) layer = l;

    int len  = layerLen[layer];
    int base = (chunk - chunkStart[layer]) * CHUNK;
    int n    = min(CHUNK, len - base);

    // ---- build coef slice in smem --------------------------------------
    if (layer < 5) {
        const float* mass; int hh, wOff;
        switch (layer) {
            case 0: mass = m0; hh = 729; wOff =   0; break;
            case 1: mass = m1; hh = 729; wOff =  64; break;
            case 2: mass = m2; hh = 169; wOff = 256; break;
            case 3: mass = m3; hh = 169; wOff = 640; break;
            default: mass = m4; hh = 169; wOff = 896; break;
        }
        for (int p = threadIdx.x; p < n; p += TPB) {
            int q  = base + p;
            int c  = q / hh;
            int hw = q - c * hh;
            s_coef[p] = __ldg(mass + hw) * __ldg(W + wOff + c);
        }
    } else if (layer < 7) {
        // fc0 / fc1: zero then scatter the 1024 selected slots that land here
        for (int p = threadIdx.x; p < n; p += TPB) s_coef[p] = 0.0f;
        __syncthreads();
        const void* ip = (layer == 5) ? i0 : i1;
        int wBase = (layer == 5) ? 1152 : 2176;
        long long probe = ((const long long*)ip)[1];
        bool is64 = (probe >= 0 && probe < 4096);
        float s = __ldg(mfc);
        for (int k = threadIdx.x; k < 1024; k += TPB) {
            int v = idx_at(ip, is64, k);
            if (v >= base && v < base + n)
                s_coef[v - base] = s * __ldg(W + wBase + k);
        }
    } else {
        float s = __ldg(mfc);
        for (int p = threadIdx.x; p < n; p += TPB)
            s_coef[p] = s * __ldg(W + 3200 + p);
    }
    __syncthreads();

    // ---- streaming dot over BPB batches --------------------------------
    const float* in;
    switch (layer) {
        case 0: in = f0; break; case 1: in = f1; break;
        case 2: in = f2; break; case 3: in = f3; break;
        case 4: in = f4; break; case 5: in = c0; break;
        case 6: in = c1; break; default: in = c2; break;
    }
    int b0 = blockIdx.y * BPB;
    const float*  p0  = in + (size_t)b0 * len + base;
    const float4* cf4 = (const float4*)s_coef;
    int n4 = n >> 2;                 // every chunk length is a multiple of 4

    float acc[BPB];
#pragma unroll
    for (int r = 0; r < BPB; r++) acc[r] = 0.f;

    for (int i = threadIdx.x; i < n4; i += TPB) {
        float4 cv = cf4[i];
#pragma unroll
        for (int r = 0; r < BPB; r++) {
            float4 v = __ldcs((const float4*)(p0 + (size_t)r * len) + i);
            acc[r] += cv.x*v.x + cv.y*v.y + cv.z*v.z + cv.w*v.w;
        }
    }

    // ---- block reduction ------------------------------------------------
#pragma unroll
    for (int off = 16; off > 0; off >>= 1)
#pragma unroll
        for (int r = 0; r < BPB; r++)
            acc[r] += __shfl_down_sync(0xFFFFFFFFu, acc[r], off);

    int warp = threadIdx.x >> 5, lane = threadIdx.x & 31;
    if (lane == 0)
#pragma unroll
        for (int r = 0; r < BPB; r++) sred[r][warp] = acc[r];
    __syncthreads();
    if (threadIdx.x < BPB) {
        float t = 0.f;
#pragma unroll
        for (int w = 0; w < TPB / 32; w++) t += sred[threadIdx.x][w];
        g_scratch[(size_t)(b0 + threadIdx.x) * NCHUNK + chunk] = t;
    }
    __threadfence();
    __syncthreads();
    if (threadIdx.x == 0) {
        int old = atomicAdd(&g_cnt[blockIdx.y], 1);
        sIsLast = (old == NCHUNK - 1);
    }
    __syncthreads();

    // ---- last block of this y-group finishes the 8 outputs --------------
    if (sIsLast) {
        if (warp < BPB) {
            const float* sc = g_scratch + (size_t)(b0 + warp) * NCHUNK;
            float t = 0.f;
            // fixed per-lane ascending order -> deterministic sum
            for (int j = lane; j < NCHUNK; j += 32) t += __ldcg(sc + j);
#pragma unroll
            for (int off = 16; off > 0; off >>= 1)
                t += __shfl_down_sync(0xFFFFFFFFu, t, off);
            if (lane == 0) out[b0 + warp] = t + __ldg(bias);
        }
        if (threadIdx.x == 0) g_cnt[blockIdx.y] = 0;   // ready for next replay
    }
}

// ---------------------------------------------------------------------------
// Host launcher. Inputs identified by element count (stable within groups).
// ---------------------------------------------------------------------------
extern "C" void kernel_launch(void* const* d_in, const int* in_sizes, int n_in,
                              void* d_out, int out_size)
{
    const float *f[5] = {0}, *fc[3] = {0}, *mass[5] = {0}, *W = 0, *bias = 0, *mfc = 0;
    const void  *idx[2] = {0};
    int nf34 = 0, nfc01 = 0, nidx = 0, n729 = 0, n169 = 0, nOne = 0;

    for (int i = 0; i < n_in; i++) {
        int sz = in_sizes[i];
        const void* p = d_in[i];
        if      (sz == 23887872) f[0] = (const float*)p;
        else if (sz == 71663616) f[1] = (const float*)p;
        else if (sz == 33226752) f[2] = (const float*)p;
        else if (sz == 22151168) { if (nf34 < 2) f[3 + nf34++] = (const float*)p; }
        else if (sz ==  2097152) { if (nfc01 < 2) fc[nfc01++] = (const float*)p; }
        else if (sz ==   512000) fc[2] = (const float*)p;
        else if (sz ==     1024) { if (nidx < 2) idx[nidx++] = p; }
        else if (sz ==     4200) W = (const float*)p;
        else if (sz ==      729) { if (n729 < 2) mass[n729++] = (const float*)p; }
        else if (sz ==      169) { if (n169 < 3) mass[2 + n169++] = (const float*)p; }
        else if (sz ==        1) { if (nOne++ == 0) mfc = (const float*)p; else bias = (const float*)p; }
    }

    fused_dot<<<dim3(NCHUNK, NYGRP), TPB>>>(
        f[0], f[1], f[2], f[3], f[4], fc[0], fc[1], fc[2],
        mass[0], mass[1], mass[2], mass[3], mass[4],
        W, mfc, idx[0], idx[1], bias, (float*)d_out);
}